// round 16
// baseline (speedup 1.0000x reference)
#include <cuda_runtime.h>
#include <cuda_fp16.h>

#define MAXN 100000
#define MAXE 1600000
#define LOG2E 1.4426950408889634f
#define DBUCK 1024

// ---------------- scratch (device globals, no allocation allowed) ----------
__device__ __half g_h1h[MAXN * 128];
__device__ __half g_hrh[MAXN * 128];
__device__ __half g_h2h[MAXN * 32];
__device__ float  g_as1[MAXN * 4];     // pre-scaled by log2(e)
__device__ float  g_ad1[MAXN * 4];
__device__ float  g_as2[MAXN];
__device__ float  g_ad2[MAXN];
__device__ float  g_w1r[128 * 128];    // rna-tf32 pre-rounded W1
__device__ float  g_w2r[128 * 32];     // rna-tf32 pre-rounded W2
__device__ int    g_deg[MAXN];
__device__ int    g_off[MAXN + 1];
__device__ int    g_pos[MAXN];
__device__ int    g_ssrc[MAXE];
__device__ int    g_bsum[512];
__device__ int    g_dh[DBUCK];         // degree histogram (descending key)
__device__ int    g_dc[DBUCK];         // scatter cursors
__device__ int    g_perm[MAXN];        // dsts sorted by degree (descending)

__device__ __forceinline__ float lrelu(float x) { return x > 0.f ? x : 0.2f * x; }

__device__ __forceinline__ unsigned tf32(float f) {
    unsigned u;
    asm("cvt.rna.tf32.f32 %0, %1;" : "=r"(u) : "f"(f));
    return u;
}

__device__ __forceinline__ void mma_tf32(float* d, const unsigned* a, unsigned b0, unsigned b1) {
    asm volatile(
        "mma.sync.aligned.m16n8k8.row.col.f32.tf32.tf32.f32 "
        "{%0,%1,%2,%3}, {%4,%5,%6,%7}, {%8,%9}, {%0,%1,%2,%3};"
        : "+f"(d[0]), "+f"(d[1]), "+f"(d[2]), "+f"(d[3])
        : "r"(a[0]), "r"(a[1]), "r"(a[2]), "r"(a[3]), "r"(b0), "r"(b1));
}

__device__ __forceinline__ void cp_async16(float* smem_dst, const void* gmem_src, bool pred) {
    unsigned sa = (unsigned)__cvta_generic_to_shared(smem_dst);
    int sz = pred ? 16 : 0;
    asm volatile("cp.async.cg.shared.global [%0], [%1], 16, %2;"
                 :: "r"(sa), "l"(gmem_src), "r"(sz));
}
#define CP_COMMIT() asm volatile("cp.async.commit_group;")
#define CP_WAIT(N)  asm volatile("cp.async.wait_group %0;" :: "n"(N))

// -------- pre-round both weight matrices to rna-tf32 (one tiny launch) -----
__global__ void round_weights(const float* __restrict__ w1, float* __restrict__ w1r, int sz1,
                              const float* __restrict__ w2, float* __restrict__ w2r, int sz2) {
    int i = blockIdx.x * blockDim.x + threadIdx.x;
    if (i < sz1) w1r[i] = __uint_as_float(tf32(w1[i]));
    else if (i < sz1 + sz2) w2r[i - sz1] = __uint_as_float(tf32(w2[i - sz1]));
}

// ---------------- tf32 tensor-core GEMM + fused attention dots -------------
template <int BN, int HT, typename TIN>
__global__ __launch_bounds__(128)
void gemm_tf32(const TIN* __restrict__ X, const float* __restrict__ W,
               __half* __restrict__ Yh,
               const float* __restrict__ a_src, const float* __restrict__ a_dst,
               float* __restrict__ as_, float* __restrict__ ad_,
               int n, int nout) {
    constexpr int BM = 128, BK = 32;
    constexpr int NT = BN / 8;
    constexpr int NHEAD = BN / 32;
    extern __shared__ float smem[];
    float* xsf = smem;                    // [2][BM][36]
    float* wsf = smem + 2 * BM * 36;      // [2][BK][72]
    __shared__ float s_asrc[BN], s_adst[BN];
#define XS(b, r, c) xsf[(((b) * BM) + (r)) * 36 + (c)]
#define WS(b, r, c) wsf[(((b) * BK) + (r)) * 72 + (c)]

    const int tid = threadIdx.x;
    const int warp = tid >> 5;
    const int lane = tid & 31;
    const int g = lane >> 2;
    const int tg = lane & 3;
    const int row0 = blockIdx.x * BM;
    const int col0 = blockIdx.y * BN;
    const int m0 = warp * 32;

    if (tid < BN) {
        s_asrc[tid] = a_src[col0 + tid];
        s_adst[tid] = a_dst[col0 + tid];
    }

    float acc[2][NT][4];
    #pragma unroll
    for (int mi = 0; mi < 2; mi++)
        #pragma unroll
        for (int ni = 0; ni < NT; ni++)
            #pragma unroll
            for (int q = 0; q < 4; q++) acc[mi][ni][q] = 0.f;

    auto issue_tile = [&](int kIter, int buf) {
        const int k0 = kIter * BK;
        if constexpr (sizeof(TIN) == 4) {
            #pragma unroll
            for (int p = 0; p < 8; p++) {
                int c = p * 128 + tid;
                int r = c >> 3, q = c & 7;
                bool valid = (row0 + r) < n;
                int grow = valid ? (row0 + r) : (n - 1);
                cp_async16(&XS(buf, r, q * 4),
                           X + (size_t)grow * 128 + k0 + q * 4, valid);
            }
        } else {
            #pragma unroll
            for (int p = 0; p < 4; p++) {
                int c = p * 128 + tid;
                int r = c >> 2, q = c & 3;
                bool valid = (row0 + r) < n;
                uint4 u = make_uint4(0, 0, 0, 0);
                if (valid) u = *(const uint4*)&X[(size_t)(row0 + r) * 128 + k0 + q * 8];
                float2 f0 = __half22float2(*(__half2*)&u.x);
                float2 f1 = __half22float2(*(__half2*)&u.y);
                float2 f2 = __half22float2(*(__half2*)&u.z);
                float2 f3 = __half22float2(*(__half2*)&u.w);
                int cb = q * 8;
                XS(buf, r, cb + 0) = f0.x; XS(buf, r, cb + 1) = f0.y;
                XS(buf, r, cb + 2) = f1.x; XS(buf, r, cb + 3) = f1.y;
                XS(buf, r, cb + 4) = f2.x; XS(buf, r, cb + 5) = f2.y;
                XS(buf, r, cb + 6) = f3.x; XS(buf, r, cb + 7) = f3.y;
            }
        }
        #pragma unroll
        for (int p = 0; p < (BK * BN / 4) / 128; p++) {
            int c = p * 128 + tid;
            int r = c / (BN / 4), c4 = c % (BN / 4);
            cp_async16(&WS(buf, r, c4 * 4),
                       W + (size_t)(k0 + r) * nout + col0 + c4 * 4, true);
        }
        CP_COMMIT();
    };

    issue_tile(0, 0);
    #pragma unroll
    for (int it = 0; it < 4; it++) {
        const int buf = it & 1;
        if (it < 3) issue_tile(it + 1, buf ^ 1);
        if (it < 3) { CP_WAIT(1); } else { CP_WAIT(0); }
        __syncthreads();
        #pragma unroll
        for (int kk = 0; kk < BK; kk += 8) {
            unsigned afrag[2][4];
            #pragma unroll
            for (int mi = 0; mi < 2; mi++) {
                int r = m0 + mi * 16 + g;
                if constexpr (sizeof(TIN) == 4) {
                    afrag[mi][0] = tf32(XS(buf, r, kk + tg));
                    afrag[mi][1] = tf32(XS(buf, r + 8, kk + tg));
                    afrag[mi][2] = tf32(XS(buf, r, kk + tg + 4));
                    afrag[mi][3] = tf32(XS(buf, r + 8, kk + tg + 4));
                } else {
                    afrag[mi][0] = __float_as_uint(XS(buf, r, kk + tg));
                    afrag[mi][1] = __float_as_uint(XS(buf, r + 8, kk + tg));
                    afrag[mi][2] = __float_as_uint(XS(buf, r, kk + tg + 4));
                    afrag[mi][3] = __float_as_uint(XS(buf, r + 8, kk + tg + 4));
                }
            }
            #pragma unroll
            for (int ni = 0; ni < NT; ni++) {
                unsigned b0 = __float_as_uint(WS(buf, kk + tg, ni * 8 + g));
                unsigned b1 = __float_as_uint(WS(buf, kk + tg + 4, ni * 8 + g));
                mma_tf32(acc[0][ni], afrag[0], b0, b1);
                mma_tf32(acc[1][ni], afrag[1], b0, b1);
            }
        }
        __syncthreads();
    }

    const int hd0 = col0 / 32;
    #pragma unroll
    for (int mi = 0; mi < 2; mi++) {
        #pragma unroll
        for (int half = 0; half < 2; half++) {
            int row = row0 + m0 + mi * 16 + g + half * 8;
            float sv[NHEAD], dv[NHEAD];
            #pragma unroll
            for (int h = 0; h < NHEAD; h++) { sv[h] = 0.f; dv[h] = 0.f; }
            #pragma unroll
            for (int ni = 0; ni < NT; ni++) {
                int j = ni * 8 + tg * 2;
                float va = acc[mi][ni][half * 2 + 0];
                float vb = acc[mi][ni][half * 2 + 1];
                int h = (NHEAD == 1) ? 0 : (ni / (NT / 2));
                sv[h] += va * s_asrc[j] + vb * s_asrc[j + 1];
                dv[h] += va * s_adst[j] + vb * s_adst[j + 1];
            }
            #pragma unroll
            for (int h = 0; h < NHEAD; h++) {
                sv[h] += __shfl_xor_sync(0xffffffffu, sv[h], 1);
                sv[h] += __shfl_xor_sync(0xffffffffu, sv[h], 2);
                dv[h] += __shfl_xor_sync(0xffffffffu, dv[h], 1);
                dv[h] += __shfl_xor_sync(0xffffffffu, dv[h], 2);
            }
            if (row < n) {
                if (tg == 0) {
                    #pragma unroll
                    for (int h = 0; h < NHEAD; h++) {
                        as_[row * HT + hd0 + h] = sv[h] * LOG2E;
                        ad_[row * HT + hd0 + h] = dv[h] * LOG2E;
                    }
                }
                int c = row * nout + col0 + tg * 2;
                #pragma unroll
                for (int ni = 0; ni < NT; ni++)
                    *(__half2*)&Yh[c + ni * 8] =
                        __floats2half2_rn(acc[mi][ni][half * 2], acc[mi][ni][half * 2 + 1]);
            }
        }
    }
#undef XS
#undef WS
}

// ---------------- CSR build --------------------------------------------------
__global__ void hist_kernel(const int* __restrict__ dst, int E, int* __restrict__ deg) {
    int e = blockIdx.x * blockDim.x + threadIdx.x;
    if (e < E) atomicAdd(&deg[dst[e]], 1);
}

__global__ __launch_bounds__(256)
void scan_part(const int* __restrict__ deg, int* __restrict__ bsum, int n) {
    int i = blockIdx.x * 256 + threadIdx.x;
    int v = (i < n) ? deg[i] : 0;
    #pragma unroll
    for (int o = 16; o; o >>= 1) v += __shfl_xor_sync(0xffffffffu, v, o);
    __shared__ int s[8];
    if ((threadIdx.x & 31) == 0) s[threadIdx.x >> 5] = v;
    __syncthreads();
    if (threadIdx.x == 0) {
        int t = 0;
        #pragma unroll
        for (int k = 0; k < 8; k++) t += s[k];
        bsum[blockIdx.x] = t;
    }
}

__global__ __launch_bounds__(512)
void scan_mid(int* __restrict__ bsum, int nb) {
    __shared__ int s[512];
    int t = threadIdx.x;
    int v = (t < nb) ? bsum[t] : 0;
    s[t] = v;
    __syncthreads();
    #pragma unroll
    for (int o = 1; o < 512; o <<= 1) {
        int u = (t >= o) ? s[t - o] : 0;
        __syncthreads();
        s[t] += u;
        __syncthreads();
    }
    if (t < nb) bsum[t] = s[t] - v;
}

__global__ __launch_bounds__(256)
void scan_final(const int* __restrict__ deg, const int* __restrict__ bsum,
                int* __restrict__ off, int* __restrict__ pos, int n) {
    int i = blockIdx.x * 256 + threadIdx.x;
    int lane = threadIdx.x & 31;
    int wid = threadIdx.x >> 5;
    int v = (i < n) ? deg[i] : 0;
    int incl = v;
    #pragma unroll
    for (int o = 1; o < 32; o <<= 1) {
        int u = __shfl_up_sync(0xffffffffu, incl, o);
        if (lane >= o) incl += u;
    }
    __shared__ int wsum[8];
    if (lane == 31) wsum[wid] = incl;
    __syncthreads();
    int wbase = 0;
    #pragma unroll
    for (int k = 0; k < 8; k++) wbase += (k < wid) ? wsum[k] : 0;
    int excl = bsum[blockIdx.x] + wbase + incl - v;
    if (i < n) { off[i] = excl; pos[i] = excl; }
    if (i == n - 1) off[n] = excl + v;
}

__global__ void scatter_kernel(const int* __restrict__ src, const int* __restrict__ dst,
                               int E, int* __restrict__ pos, int* __restrict__ ssrc) {
    int e = blockIdx.x * blockDim.x + threadIdx.x;
    if (e < E) {
        int p = atomicAdd(&pos[dst[e]], 1);
        ssrc[p] = src[e];
    }
}

// -------- degree counting sort (descending): perm[k] = k-th largest-degree dst
__global__ void deg_hist(const int* __restrict__ deg, int* __restrict__ dh, int n) {
    int i = blockIdx.x * blockDim.x + threadIdx.x;
    if (i < n) {
        int key = DBUCK - 1 - min(deg[i], DBUCK - 1);   // descending
        atomicAdd(&dh[key], 1);
    }
}

__global__ __launch_bounds__(1024)
void deg_scan(const int* __restrict__ dh, int* __restrict__ dc) {
    __shared__ int s[DBUCK];
    int t = threadIdx.x;
    int v = dh[t];
    s[t] = v;
    __syncthreads();
    #pragma unroll
    for (int o = 1; o < DBUCK; o <<= 1) {
        int u = (t >= o) ? s[t - o] : 0;
        __syncthreads();
        s[t] += u;
        __syncthreads();
    }
    dc[t] = s[t] - v;   // exclusive
}

__global__ void deg_scatter(const int* __restrict__ deg, int* __restrict__ dc,
                            int* __restrict__ perm, int n) {
    int i = blockIdx.x * blockDim.x + threadIdx.x;
    if (i < n) {
        int key = DBUCK - 1 - min(deg[i], DBUCK - 1);
        int p = atomicAdd(&dc[key], 1);
        perm[p] = i;
    }
}

// -------- CSR aggregation, layer 1 (H=4, C=32): one warp per dst (perm) -----
__global__ __launch_bounds__(256)
void agg4(const int* __restrict__ perm,
          const int* __restrict__ off, const int* __restrict__ ssrc,
          const __half* __restrict__ hh,
          const float* __restrict__ as_, const float* __restrict__ ad_,
          const float* __restrict__ bias, __half* __restrict__ out, int n) {
    int widx = (blockIdx.x * blockDim.x + threadIdx.x) >> 5;
    if (widx >= n) return;
    const int d = __ldg(&perm[widx]);
    const int lane = threadIdx.x & 31;
    const int hl = lane & 15;
    const int eslot = lane >> 4;
    const int head = hl >> 2;
    const int ch = hl * 8;

    float asl = 0.f, adl = 0.f;
    if (hl < 4) { asl = __ldg(&as_[d * 4 + hl]); adl = __ldg(&ad_[d * 4 + hl]); }

    float wself = (hl < 4) ? exp2f(lrelu(asl + adl)) : 0.f;
    float den_part = (eslot == 0 && hl < 4) ? wself : 0.f;

    float acc[8];
    #pragma unroll
    for (int k = 0; k < 8; k++) acc[k] = 0.f;
    float whs = __shfl_sync(0xffffffffu, wself, head);
    if (eslot == 0) {
        uint4 rs = *(const uint4*)&hh[d * 128 + ch];
        float2 f0 = __half22float2(*(__half2*)&rs.x);
        float2 f1 = __half22float2(*(__half2*)&rs.y);
        float2 f2 = __half22float2(*(__half2*)&rs.z);
        float2 f3 = __half22float2(*(__half2*)&rs.w);
        acc[0] = whs * f0.x; acc[1] = whs * f0.y;
        acc[2] = whs * f1.x; acc[3] = whs * f1.y;
        acc[4] = whs * f2.x; acc[5] = whs * f2.y;
        acc[6] = whs * f3.x; acc[7] = whs * f3.y;
    }

    const int end = off[d + 1];
    #pragma unroll 4
    for (int i = off[d]; i < end; i += 2) {
        const int e = i + eslot;
        const bool v = e < end;
        int se = 0;
        if (v) se = __ldg(&ssrc[e]);
        float we = 0.f;
        if (hl < 4 && v) we = exp2f(lrelu(__ldg(&as_[se * 4 + hl]) + adl));
        den_part += we;
        uint4 r = *(const uint4*)&hh[se * 128 + ch];
        float w = __shfl_sync(0xffffffffu, we, (lane & 16) | head);
        float2 f0 = __half22float2(*(__half2*)&r.x);
        float2 f1 = __half22float2(*(__half2*)&r.y);
        float2 f2 = __half22float2(*(__half2*)&r.z);
        float2 f3 = __half22float2(*(__half2*)&r.w);
        acc[0] += w * f0.x; acc[1] += w * f0.y;
        acc[2] += w * f1.x; acc[3] += w * f1.y;
        acc[4] += w * f2.x; acc[5] += w * f2.y;
        acc[6] += w * f3.x; acc[7] += w * f3.y;
    }

    den_part += __shfl_xor_sync(0xffffffffu, den_part, 16);
    #pragma unroll
    for (int k = 0; k < 8; k++)
        acc[k] += __shfl_xor_sync(0xffffffffu, acc[k], 16);

    float inv = 1.f / den_part;
    float invh = __shfl_sync(0xffffffffu, inv, head);

    if (eslot == 0) {
        float4 b0 = *(const float4*)&bias[ch];
        float4 b1 = *(const float4*)&bias[ch + 4];
        float o0 = fmaxf(acc[0] * invh + b0.x, 0.f);
        float o1 = fmaxf(acc[1] * invh + b0.y, 0.f);
        float o2 = fmaxf(acc[2] * invh + b0.z, 0.f);
        float o3 = fmaxf(acc[3] * invh + b0.w, 0.f);
        float o4 = fmaxf(acc[4] * invh + b1.x, 0.f);
        float o5 = fmaxf(acc[5] * invh + b1.y, 0.f);
        float o6 = fmaxf(acc[6] * invh + b1.z, 0.f);
        float o7 = fmaxf(acc[7] * invh + b1.w, 0.f);
        uint4 o;
        *(__half2*)&o.x = __floats2half2_rn(o0, o1);
        *(__half2*)&o.y = __floats2half2_rn(o2, o3);
        *(__half2*)&o.z = __floats2half2_rn(o4, o5);
        *(__half2*)&o.w = __floats2half2_rn(o6, o7);
        *(uint4*)&out[d * 128 + ch] = o;
    }
}

// -------- CSR aggregation, layer 2 (H=1, C=32): one warp per dst (perm) -----
__global__ __launch_bounds__(256)
void agg1(const int* __restrict__ perm,
          const int* __restrict__ off, const int* __restrict__ ssrc,
          const __half* __restrict__ hh,
          const float* __restrict__ as_, const float* __restrict__ ad_,
          const float* __restrict__ bias, float* __restrict__ out, int n) {
    int widx = (blockIdx.x * blockDim.x + threadIdx.x) >> 5;
    if (widx >= n) return;
    const int d = __ldg(&perm[widx]);
    const int lane = threadIdx.x & 31;
    const int hl = lane & 7;
    const int eslot = lane >> 3;       // 0..3
    const int ch = hl * 4;

    const float adv = __ldg(&ad_[d]);
    const float wself = exp2f(lrelu(__ldg(&as_[d]) + adv));
    float den_part = (lane == 0) ? wself : 0.f;

    float4 acc = make_float4(0.f, 0.f, 0.f, 0.f);
    if (eslot == 0) {
        uint2 u = *(const uint2*)&hh[d * 32 + ch];
        float2 f0 = __half22float2(*(__half2*)&u.x);
        float2 f1 = __half22float2(*(__half2*)&u.y);
        acc.x = wself * f0.x; acc.y = wself * f0.y;
        acc.z = wself * f1.x; acc.w = wself * f1.y;
    }

    const int end = off[d + 1];
    #pragma unroll 4
    for (int i = off[d]; i < end; i += 4) {
        const int e = i + eslot;
        const bool v = e < end;
        int se = 0;
        if (v) se = __ldg(&ssrc[e]);
        float we = 0.f;
        if (hl == 0 && v) we = exp2f(lrelu(__ldg(&as_[se]) + adv));
        den_part += we;
        uint2 u = *(const uint2*)&hh[se * 32 + ch];
        float w = __shfl_sync(0xffffffffu, we, lane & 24);
        float2 f0 = __half22float2(*(__half2*)&u.x);
        float2 f1 = __half22float2(*(__half2*)&u.y);
        acc.x += w * f0.x; acc.y += w * f0.y;
        acc.z += w * f1.x; acc.w += w * f1.y;
    }

    den_part += __shfl_xor_sync(0xffffffffu, den_part, 8);
    den_part += __shfl_xor_sync(0xffffffffu, den_part, 16);
    acc.x += __shfl_xor_sync(0xffffffffu, acc.x, 8);
    acc.y += __shfl_xor_sync(0xffffffffu, acc.y, 8);
    acc.z += __shfl_xor_sync(0xffffffffu, acc.z, 8);
    acc.w += __shfl_xor_sync(0xffffffffu, acc.w, 8);
    acc.x += __shfl_xor_sync(0xffffffffu, acc.x, 16);
    acc.y += __shfl_xor_sync(0xffffffffu, acc.y, 16);
    acc.z += __shfl_xor_sync(0xffffffffu, acc.z, 16);
    acc.w += __shfl_xor_sync(0xffffffffu, acc.w, 16);

    float inv = 1.f / den_part;
    float invb = __shfl_sync(0xffffffffu, inv, 0);

    if (eslot == 0) {
        float4 b = *(const float4*)&bias[ch];
        float4 o;
        o.x = acc.x * invb + b.x; o.y = acc.y * invb + b.y;
        o.z = acc.z * invb + b.z; o.w = acc.w * invb + b.w;
        *(float4*)&out[d * 32 + ch] = o;
    }
}

// ---------------------------------------------------------------------------
extern "C" void kernel_launch(void* const* d_in, const int* in_sizes, int n_in,
                              void* d_out, int out_size) {
    const float* x    = (const float*)d_in[0];
    const int*   ei   = (const int*)d_in[1];
    const float* W1   = (const float*)d_in[2];
    const float* asr1 = (const float*)d_in[3];
    const float* adt1 = (const float*)d_in[4];
    const float* b1   = (const float*)d_in[5];
    const float* W2   = (const float*)d_in[6];
    const float* asr2 = (const float*)d_in[7];
    const float* adt2 = (const float*)d_in[8];
    const float* b2   = (const float*)d_in[9];
    float* out = (float*)d_out;

    const int n = in_sizes[0] / 128;
    const int E = in_sizes[1] / 2;
    const int* src = ei;
    const int* dst = ei + E;

    float *as1, *ad1, *as2, *ad2, *w1r, *w2r;
    __half *h1h, *hrh, *h2h;
    int *deg, *off, *pos, *ssrc, *bsum, *dh, *dc, *perm;
    cudaGetSymbolAddress((void**)&h1h,  g_h1h);
    cudaGetSymbolAddress((void**)&hrh,  g_hrh);
    cudaGetSymbolAddress((void**)&h2h,  g_h2h);
    cudaGetSymbolAddress((void**)&as1,  g_as1);
    cudaGetSymbolAddress((void**)&ad1,  g_ad1);
    cudaGetSymbolAddress((void**)&as2,  g_as2);
    cudaGetSymbolAddress((void**)&ad2,  g_ad2);
    cudaGetSymbolAddress((void**)&w1r,  g_w1r);
    cudaGetSymbolAddress((void**)&w2r,  g_w2r);
    cudaGetSymbolAddress((void**)&deg,  g_deg);
    cudaGetSymbolAddress((void**)&off,  g_off);
    cudaGetSymbolAddress((void**)&pos,  g_pos);
    cudaGetSymbolAddress((void**)&ssrc, g_ssrc);
    cudaGetSymbolAddress((void**)&bsum, g_bsum);
    cudaGetSymbolAddress((void**)&dh,   g_dh);
    cudaGetSymbolAddress((void**)&dc,   g_dc);
    cudaGetSymbolAddress((void**)&perm, g_perm);

    const int GEMM_SMEM = (2 * 128 * 36 + 2 * 32 * 72) * 4;   // 55296 B

    static cudaStream_t s2 = nullptr, s3 = nullptr;
    static cudaEvent_t evFork = nullptr, evJoin = nullptr, evDeg = nullptr, evPerm = nullptr;
    if (!s2) {
        cudaStreamCreateWithFlags(&s2, cudaStreamNonBlocking);
        cudaStreamCreateWithFlags(&s3, cudaStreamNonBlocking);
        cudaEventCreateWithFlags(&evFork, cudaEventDisableTiming);
        cudaEventCreateWithFlags(&evJoin, cudaEventDisableTiming);
        cudaEventCreateWithFlags(&evDeg, cudaEventDisableTiming);
        cudaEventCreateWithFlags(&evPerm, cudaEventDisableTiming);
        cudaFuncSetAttribute(gemm_tf32<64, 4, float>,
                             cudaFuncAttributeMaxDynamicSharedMemorySize, GEMM_SMEM);
        cudaFuncSetAttribute(gemm_tf32<32, 1, __half>,
                             cudaFuncAttributeMaxDynamicSharedMemorySize, GEMM_SMEM);
    }

    const int nb128 = (n + 127) / 128;
    const int eb = (E + 255) / 256;
    const int nwarp_blocks = (n * 32 + 255) / 256;
    const int nscan = (n + 255) / 256;
    const int SZ1 = 128 * 128, SZ2 = 128 * 32;

    // ---- fork: CSR build on side stream ----
    cudaEventRecord(evFork, 0);
    cudaStreamWaitEvent(s2, evFork, 0);
    cudaMemsetAsync(deg, 0, n * sizeof(int), s2);
    hist_kernel<<<eb, 256, 0, s2>>>(dst, E, deg);
    cudaEventRecord(evDeg, s2);
    scan_part<<<nscan, 256, 0, s2>>>(deg, bsum, n);
    scan_mid<<<1, 512, 0, s2>>>(bsum, nscan);
    scan_final<<<nscan, 256, 0, s2>>>(deg, bsum, off, pos, n);
    scatter_kernel<<<eb, 256, 0, s2>>>(src, dst, E, pos, ssrc);
    cudaEventRecord(evJoin, s2);

    // ---- stream 3: degree counting sort (overlaps scan chain + gemm1) ----
    cudaStreamWaitEvent(s3, evDeg, 0);
    cudaMemsetAsync(dh, 0, DBUCK * sizeof(int), s3);
    deg_hist<<<nscan, 256, 0, s3>>>(deg, dh, n);
    deg_scan<<<1, DBUCK, 0, s3>>>(dh, dc);
    deg_scatter<<<nscan, 256, 0, s3>>>(deg, dc, perm, n);
    cudaEventRecord(evPerm, s3);

    // ---- main stream: pre-round weights, then layer-1 GEMM (+fused dots) ----
    round_weights<<<(SZ1 + SZ2 + 255) / 256, 256>>>(W1, w1r, SZ1, W2, w2r, SZ2);
    gemm_tf32<64, 4, float><<<dim3(nb128, 2), 128, GEMM_SMEM>>>(
        x, w1r, h1h, asr1, adt1, as1, ad1, n, 128);

    // ---- join ----
    cudaStreamWaitEvent(0, evJoin, 0);
    cudaStreamWaitEvent(0, evPerm, 0);
    agg4<<<nwarp_blocks, 256>>>(perm, off, ssrc, h1h, as1, ad1, b1, hrh, n);

    // ---- Layer 2 ----
    gemm_tf32<32, 1, __half><<<dim3(nb128, 1), 128, GEMM_SMEM>>>(
        hrh, w2r, h2h, asr2, adt2, as2, ad2, n, 32);
    agg1<<<nwarp_blocks, 256>>>(perm, off, ssrc, h2h, as2, ad2, b2, out, n);
}

// round 17
// speedup vs baseline: 1.1992x; 1.1992x over previous
#include <cuda_runtime.h>
#include <cuda_fp16.h>

#define MAXN 100000
#define MAXE 1600000
#define LOG2E 1.4426950408889634f

// ---------------- scratch (device globals, no allocation allowed) ----------
__device__ __half g_h1h[MAXN * 128];
__device__ __half g_hrh[MAXN * 128];
__device__ __half g_h2h[MAXN * 32];
__device__ float  g_as1[MAXN * 4];     // pre-scaled by log2(e)
__device__ float  g_ad1[MAXN * 4];
__device__ float  g_as2[MAXN];
__device__ float  g_ad2[MAXN];
__device__ float  g_w1r[128 * 128];    // rna-tf32 pre-rounded W1
__device__ float  g_w2r[128 * 32];     // rna-tf32 pre-rounded W2
__device__ int    g_deg[MAXN];
__device__ int    g_off[MAXN + 1];
__device__ int    g_pos[MAXN];
__device__ int    g_ssrc[MAXE];
__device__ int    g_bsum[512];

__device__ __forceinline__ float lrelu(float x) { return x > 0.f ? x : 0.2f * x; }

__device__ __forceinline__ unsigned tf32(float f) {
    unsigned u;
    asm("cvt.rna.tf32.f32 %0, %1;" : "=r"(u) : "f"(f));
    return u;
}

__device__ __forceinline__ void mma_tf32(float* d, const unsigned* a, unsigned b0, unsigned b1) {
    asm volatile(
        "mma.sync.aligned.m16n8k8.row.col.f32.tf32.tf32.f32 "
        "{%0,%1,%2,%3}, {%4,%5,%6,%7}, {%8,%9}, {%0,%1,%2,%3};"
        : "+f"(d[0]), "+f"(d[1]), "+f"(d[2]), "+f"(d[3])
        : "r"(a[0]), "r"(a[1]), "r"(a[2]), "r"(a[3]), "r"(b0), "r"(b1));
}

__device__ __forceinline__ void cp_async16(float* smem_dst, const void* gmem_src, bool pred) {
    unsigned sa = (unsigned)__cvta_generic_to_shared(smem_dst);
    int sz = pred ? 16 : 0;
    asm volatile("cp.async.cg.shared.global [%0], [%1], 16, %2;"
                 :: "r"(sa), "l"(gmem_src), "r"(sz));
}
#define CP_COMMIT() asm volatile("cp.async.commit_group;")
#define CP_WAIT(N)  asm volatile("cp.async.wait_group %0;" :: "n"(N))

// -------- pre-round both weight matrices to rna-tf32 (one tiny launch) -----
__global__ void round_weights(const float* __restrict__ w1, float* __restrict__ w1r, int sz1,
                              const float* __restrict__ w2, float* __restrict__ w2r, int sz2) {
    int i = blockIdx.x * blockDim.x + threadIdx.x;
    if (i < sz1) w1r[i] = __uint_as_float(tf32(w1[i]));
    else if (i < sz1 + sz2) w2r[i - sz1] = __uint_as_float(tf32(w2[i - sz1]));
}

// ---------------- tf32 tensor-core GEMM + fused attention dots -------------
template <int BN, int HT, typename TIN>
__global__ __launch_bounds__(128)
void gemm_tf32(const TIN* __restrict__ X, const float* __restrict__ W,
               __half* __restrict__ Yh,
               const float* __restrict__ a_src, const float* __restrict__ a_dst,
               float* __restrict__ as_, float* __restrict__ ad_,
               int n, int nout) {
    constexpr int BM = 128, BK = 32;
    constexpr int NT = BN / 8;
    constexpr int NHEAD = BN / 32;
    extern __shared__ float smem[];
    float* xsf = smem;                    // [2][BM][36]
    float* wsf = smem + 2 * BM * 36;      // [2][BK][72]
    __shared__ float s_asrc[BN], s_adst[BN];
#define XS(b, r, c) xsf[(((b) * BM) + (r)) * 36 + (c)]
#define WS(b, r, c) wsf[(((b) * BK) + (r)) * 72 + (c)]

    const int tid = threadIdx.x;
    const int warp = tid >> 5;
    const int lane = tid & 31;
    const int g = lane >> 2;
    const int tg = lane & 3;
    const int row0 = blockIdx.x * BM;
    const int col0 = blockIdx.y * BN;
    const int m0 = warp * 32;

    if (tid < BN) {
        s_asrc[tid] = a_src[col0 + tid];
        s_adst[tid] = a_dst[col0 + tid];
    }

    float acc[2][NT][4];
    #pragma unroll
    for (int mi = 0; mi < 2; mi++)
        #pragma unroll
        for (int ni = 0; ni < NT; ni++)
            #pragma unroll
            for (int q = 0; q < 4; q++) acc[mi][ni][q] = 0.f;

    auto issue_tile = [&](int kIter, int buf) {
        const int k0 = kIter * BK;
        if constexpr (sizeof(TIN) == 4) {
            #pragma unroll
            for (int p = 0; p < 8; p++) {
                int c = p * 128 + tid;
                int r = c >> 3, q = c & 7;
                bool valid = (row0 + r) < n;
                int grow = valid ? (row0 + r) : (n - 1);
                cp_async16(&XS(buf, r, q * 4),
                           X + (size_t)grow * 128 + k0 + q * 4, valid);
            }
        } else {
            #pragma unroll
            for (int p = 0; p < 4; p++) {
                int c = p * 128 + tid;
                int r = c >> 2, q = c & 3;
                bool valid = (row0 + r) < n;
                uint4 u = make_uint4(0, 0, 0, 0);
                if (valid) u = *(const uint4*)&X[(size_t)(row0 + r) * 128 + k0 + q * 8];
                float2 f0 = __half22float2(*(__half2*)&u.x);
                float2 f1 = __half22float2(*(__half2*)&u.y);
                float2 f2 = __half22float2(*(__half2*)&u.z);
                float2 f3 = __half22float2(*(__half2*)&u.w);
                int cb = q * 8;
                XS(buf, r, cb + 0) = f0.x; XS(buf, r, cb + 1) = f0.y;
                XS(buf, r, cb + 2) = f1.x; XS(buf, r, cb + 3) = f1.y;
                XS(buf, r, cb + 4) = f2.x; XS(buf, r, cb + 5) = f2.y;
                XS(buf, r, cb + 6) = f3.x; XS(buf, r, cb + 7) = f3.y;
            }
        }
        #pragma unroll
        for (int p = 0; p < (BK * BN / 4) / 128; p++) {
            int c = p * 128 + tid;
            int r = c / (BN / 4), c4 = c % (BN / 4);
            cp_async16(&WS(buf, r, c4 * 4),
                       W + (size_t)(k0 + r) * nout + col0 + c4 * 4, true);
        }
        CP_COMMIT();
    };

    issue_tile(0, 0);
    #pragma unroll
    for (int it = 0; it < 4; it++) {
        const int buf = it & 1;
        if (it < 3) issue_tile(it + 1, buf ^ 1);
        if (it < 3) { CP_WAIT(1); } else { CP_WAIT(0); }
        __syncthreads();
        #pragma unroll
        for (int kk = 0; kk < BK; kk += 8) {
            unsigned afrag[2][4];
            #pragma unroll
            for (int mi = 0; mi < 2; mi++) {
                int r = m0 + mi * 16 + g;
                if constexpr (sizeof(TIN) == 4) {
                    afrag[mi][0] = tf32(XS(buf, r, kk + tg));
                    afrag[mi][1] = tf32(XS(buf, r + 8, kk + tg));
                    afrag[mi][2] = tf32(XS(buf, r, kk + tg + 4));
                    afrag[mi][3] = tf32(XS(buf, r + 8, kk + tg + 4));
                } else {
                    afrag[mi][0] = __float_as_uint(XS(buf, r, kk + tg));
                    afrag[mi][1] = __float_as_uint(XS(buf, r + 8, kk + tg));
                    afrag[mi][2] = __float_as_uint(XS(buf, r, kk + tg + 4));
                    afrag[mi][3] = __float_as_uint(XS(buf, r + 8, kk + tg + 4));
                }
            }
            #pragma unroll
            for (int ni = 0; ni < NT; ni++) {
                unsigned b0 = __float_as_uint(WS(buf, kk + tg, ni * 8 + g));
                unsigned b1 = __float_as_uint(WS(buf, kk + tg + 4, ni * 8 + g));
                mma_tf32(acc[0][ni], afrag[0], b0, b1);
                mma_tf32(acc[1][ni], afrag[1], b0, b1);
            }
        }
        __syncthreads();
    }

    const int hd0 = col0 / 32;
    #pragma unroll
    for (int mi = 0; mi < 2; mi++) {
        #pragma unroll
        for (int half = 0; half < 2; half++) {
            int row = row0 + m0 + mi * 16 + g + half * 8;
            float sv[NHEAD], dv[NHEAD];
            #pragma unroll
            for (int h = 0; h < NHEAD; h++) { sv[h] = 0.f; dv[h] = 0.f; }
            #pragma unroll
            for (int ni = 0; ni < NT; ni++) {
                int j = ni * 8 + tg * 2;
                float va = acc[mi][ni][half * 2 + 0];
                float vb = acc[mi][ni][half * 2 + 1];
                int h = (NHEAD == 1) ? 0 : (ni / (NT / 2));
                sv[h] += va * s_asrc[j] + vb * s_asrc[j + 1];
                dv[h] += va * s_adst[j] + vb * s_adst[j + 1];
            }
            #pragma unroll
            for (int h = 0; h < NHEAD; h++) {
                sv[h] += __shfl_xor_sync(0xffffffffu, sv[h], 1);
                sv[h] += __shfl_xor_sync(0xffffffffu, sv[h], 2);
                dv[h] += __shfl_xor_sync(0xffffffffu, dv[h], 1);
                dv[h] += __shfl_xor_sync(0xffffffffu, dv[h], 2);
            }
            if (row < n) {
                if (tg == 0) {
                    #pragma unroll
                    for (int h = 0; h < NHEAD; h++) {
                        as_[row * HT + hd0 + h] = sv[h] * LOG2E;
                        ad_[row * HT + hd0 + h] = dv[h] * LOG2E;
                    }
                }
                int c = row * nout + col0 + tg * 2;
                #pragma unroll
                for (int ni = 0; ni < NT; ni++)
                    *(__half2*)&Yh[c + ni * 8] =
                        __floats2half2_rn(acc[mi][ni][half * 2], acc[mi][ni][half * 2 + 1]);
            }
        }
    }
#undef XS
#undef WS
}

// ---------------- CSR build --------------------------------------------------
__global__ void hist_kernel(const int* __restrict__ dst, int E, int* __restrict__ deg) {
    int e = blockIdx.x * blockDim.x + threadIdx.x;
    if (e < E) atomicAdd(&deg[dst[e]], 1);
}

__global__ __launch_bounds__(256)
void scan_part(const int* __restrict__ deg, int* __restrict__ bsum, int n) {
    int i = blockIdx.x * 256 + threadIdx.x;
    int v = (i < n) ? deg[i] : 0;
    #pragma unroll
    for (int o = 16; o; o >>= 1) v += __shfl_xor_sync(0xffffffffu, v, o);
    __shared__ int s[8];
    if ((threadIdx.x & 31) == 0) s[threadIdx.x >> 5] = v;
    __syncthreads();
    if (threadIdx.x == 0) {
        int t = 0;
        #pragma unroll
        for (int k = 0; k < 8; k++) t += s[k];
        bsum[blockIdx.x] = t;
    }
}

__global__ __launch_bounds__(512)
void scan_mid(int* __restrict__ bsum, int nb) {
    __shared__ int s[512];
    int t = threadIdx.x;
    int v = (t < nb) ? bsum[t] : 0;
    s[t] = v;
    __syncthreads();
    #pragma unroll
    for (int o = 1; o < 512; o <<= 1) {
        int u = (t >= o) ? s[t - o] : 0;
        __syncthreads();
        s[t] += u;
        __syncthreads();
    }
    if (t < nb) bsum[t] = s[t] - v;
}

__global__ __launch_bounds__(256)
void scan_final(const int* __restrict__ deg, const int* __restrict__ bsum,
                int* __restrict__ off, int* __restrict__ pos, int n) {
    int i = blockIdx.x * 256 + threadIdx.x;
    int lane = threadIdx.x & 31;
    int wid = threadIdx.x >> 5;
    int v = (i < n) ? deg[i] : 0;
    int incl = v;
    #pragma unroll
    for (int o = 1; o < 32; o <<= 1) {
        int u = __shfl_up_sync(0xffffffffu, incl, o);
        if (lane >= o) incl += u;
    }
    __shared__ int wsum[8];
    if (lane == 31) wsum[wid] = incl;
    __syncthreads();
    int wbase = 0;
    #pragma unroll
    for (int k = 0; k < 8; k++) wbase += (k < wid) ? wsum[k] : 0;
    int excl = bsum[blockIdx.x] + wbase + incl - v;
    if (i < n) { off[i] = excl; pos[i] = excl; }
    if (i == n - 1) off[n] = excl + v;
}

__global__ void scatter_kernel(const int* __restrict__ src, const int* __restrict__ dst,
                               int E, int* __restrict__ pos, int* __restrict__ ssrc) {
    int e = blockIdx.x * blockDim.x + threadIdx.x;
    if (e < E) {
        int p = atomicAdd(&pos[dst[e]], 1);
        ssrc[p] = src[e];
    }
}

// -------- CSR aggregation, layer 1 (H=4, C=32): one warp per dst ------------
// R12-validated loop: 2 edges/iter, exp on 8 lanes, unroll 4. 128-thr blocks.
__global__ __launch_bounds__(128)
void agg4(const int* __restrict__ off, const int* __restrict__ ssrc,
          const __half* __restrict__ hh,
          const float* __restrict__ as_, const float* __restrict__ ad_,
          const float* __restrict__ bias, __half* __restrict__ out, int n) {
    int d = (blockIdx.x * blockDim.x + threadIdx.x) >> 5;
    if (d >= n) return;
    const int lane = threadIdx.x & 31;
    const int hl = lane & 15;
    const int eslot = lane >> 4;
    const int head = hl >> 2;
    const int ch = hl * 8;

    float asl = 0.f, adl = 0.f;
    if (hl < 4) { asl = __ldg(&as_[d * 4 + hl]); adl = __ldg(&ad_[d * 4 + hl]); }

    float wself = (hl < 4) ? exp2f(lrelu(asl + adl)) : 0.f;
    float den_part = (eslot == 0 && hl < 4) ? wself : 0.f;

    float acc[8];
    #pragma unroll
    for (int k = 0; k < 8; k++) acc[k] = 0.f;
    float whs = __shfl_sync(0xffffffffu, wself, head);
    if (eslot == 0) {
        uint4 rs = *(const uint4*)&hh[d * 128 + ch];
        float2 f0 = __half22float2(*(__half2*)&rs.x);
        float2 f1 = __half22float2(*(__half2*)&rs.y);
        float2 f2 = __half22float2(*(__half2*)&rs.z);
        float2 f3 = __half22float2(*(__half2*)&rs.w);
        acc[0] = whs * f0.x; acc[1] = whs * f0.y;
        acc[2] = whs * f1.x; acc[3] = whs * f1.y;
        acc[4] = whs * f2.x; acc[5] = whs * f2.y;
        acc[6] = whs * f3.x; acc[7] = whs * f3.y;
    }

    const int end = off[d + 1];
    #pragma unroll 4
    for (int i = off[d]; i < end; i += 2) {
        const int e = i + eslot;
        const bool v = e < end;
        int se = 0;
        if (v) se = __ldg(&ssrc[e]);
        float we = 0.f;
        if (hl < 4 && v) we = exp2f(lrelu(__ldg(&as_[se * 4 + hl]) + adl));
        den_part += we;
        uint4 r = *(const uint4*)&hh[se * 128 + ch];
        float w = __shfl_sync(0xffffffffu, we, (lane & 16) | head);
        float2 f0 = __half22float2(*(__half2*)&r.x);
        float2 f1 = __half22float2(*(__half2*)&r.y);
        float2 f2 = __half22float2(*(__half2*)&r.z);
        float2 f3 = __half22float2(*(__half2*)&r.w);
        acc[0] += w * f0.x; acc[1] += w * f0.y;
        acc[2] += w * f1.x; acc[3] += w * f1.y;
        acc[4] += w * f2.x; acc[5] += w * f2.y;
        acc[6] += w * f3.x; acc[7] += w * f3.y;
    }

    den_part += __shfl_xor_sync(0xffffffffu, den_part, 16);
    #pragma unroll
    for (int k = 0; k < 8; k++)
        acc[k] += __shfl_xor_sync(0xffffffffu, acc[k], 16);

    float inv = 1.f / den_part;
    float invh = __shfl_sync(0xffffffffu, inv, head);

    if (eslot == 0) {
        float4 b0 = *(const float4*)&bias[ch];
        float4 b1 = *(const float4*)&bias[ch + 4];
        float o0 = fmaxf(acc[0] * invh + b0.x, 0.f);
        float o1 = fmaxf(acc[1] * invh + b0.y, 0.f);
        float o2 = fmaxf(acc[2] * invh + b0.z, 0.f);
        float o3 = fmaxf(acc[3] * invh + b0.w, 0.f);
        float o4 = fmaxf(acc[4] * invh + b1.x, 0.f);
        float o5 = fmaxf(acc[5] * invh + b1.y, 0.f);
        float o6 = fmaxf(acc[6] * invh + b1.z, 0.f);
        float o7 = fmaxf(acc[7] * invh + b1.w, 0.f);
        uint4 o;
        *(__half2*)&o.x = __floats2half2_rn(o0, o1);
        *(__half2*)&o.y = __floats2half2_rn(o2, o3);
        *(__half2*)&o.z = __floats2half2_rn(o4, o5);
        *(__half2*)&o.w = __floats2half2_rn(o6, o7);
        *(uint4*)&out[d * 128 + ch] = o;
    }
}

// -------- CSR aggregation, layer 2 (H=1, C=32): one warp per dst ------------
// 4 edges/iter: eslot = lane>>3 (4 slots), hl = lane&7 owns 4 channels (uint2).
__global__ __launch_bounds__(128)
void agg1(const int* __restrict__ off, const int* __restrict__ ssrc,
          const __half* __restrict__ hh,
          const float* __restrict__ as_, const float* __restrict__ ad_,
          const float* __restrict__ bias, float* __restrict__ out, int n) {
    int d = (blockIdx.x * blockDim.x + threadIdx.x) >> 5;
    if (d >= n) return;
    const int lane = threadIdx.x & 31;
    const int hl = lane & 7;
    const int eslot = lane >> 3;       // 0..3
    const int ch = hl * 4;

    const float adv = __ldg(&ad_[d]);
    const float wself = exp2f(lrelu(__ldg(&as_[d]) + adv));
    float den_part = (lane == 0) ? wself : 0.f;

    float4 acc = make_float4(0.f, 0.f, 0.f, 0.f);
    if (eslot == 0) {
        uint2 u = *(const uint2*)&hh[d * 32 + ch];
        float2 f0 = __half22float2(*(__half2*)&u.x);
        float2 f1 = __half22float2(*(__half2*)&u.y);
        acc.x = wself * f0.x; acc.y = wself * f0.y;
        acc.z = wself * f1.x; acc.w = wself * f1.y;
    }

    const int end = off[d + 1];
    #pragma unroll 4
    for (int i = off[d]; i < end; i += 4) {
        const int e = i + eslot;
        const bool v = e < end;
        int se = 0;
        if (v) se = __ldg(&ssrc[e]);
        float we = 0.f;
        if (hl == 0 && v) we = exp2f(lrelu(__ldg(&as_[se]) + adv));
        den_part += we;
        uint2 u = *(const uint2*)&hh[se * 32 + ch];     // se=0 when invalid (w=0)
        float w = __shfl_sync(0xffffffffu, we, lane & 24);   // this eslot's hl==0 lane
        float2 f0 = __half22float2(*(__half2*)&u.x);
        float2 f1 = __half22float2(*(__half2*)&u.y);
        acc.x += w * f0.x; acc.y += w * f0.y;
        acc.z += w * f1.x; acc.w += w * f1.y;
    }

    // combine the 4 eslots (xor 8 / xor 16 keep hl fixed)
    den_part += __shfl_xor_sync(0xffffffffu, den_part, 8);
    den_part += __shfl_xor_sync(0xffffffffu, den_part, 16);
    acc.x += __shfl_xor_sync(0xffffffffu, acc.x, 8);
    acc.y += __shfl_xor_sync(0xffffffffu, acc.y, 8);
    acc.z += __shfl_xor_sync(0xffffffffu, acc.z, 8);
    acc.w += __shfl_xor_sync(0xffffffffu, acc.w, 8);
    acc.x += __shfl_xor_sync(0xffffffffu, acc.x, 16);
    acc.y += __shfl_xor_sync(0xffffffffu, acc.y, 16);
    acc.z += __shfl_xor_sync(0xffffffffu, acc.z, 16);
    acc.w += __shfl_xor_sync(0xffffffffu, acc.w, 16);

    float inv = 1.f / den_part;                 // full den on lanes {0,8,16,24}
    float invb = __shfl_sync(0xffffffffu, inv, 0);

    if (eslot == 0) {
        float4 b = *(const float4*)&bias[ch];
        float4 o;
        o.x = acc.x * invb + b.x; o.y = acc.y * invb + b.y;
        o.z = acc.z * invb + b.z; o.w = acc.w * invb + b.w;
        *(float4*)&out[d * 32 + ch] = o;
    }
}

// ---------------------------------------------------------------------------
extern "C" void kernel_launch(void* const* d_in, const int* in_sizes, int n_in,
                              void* d_out, int out_size) {
    const float* x    = (const float*)d_in[0];
    const int*   ei   = (const int*)d_in[1];
    const float* W1   = (const float*)d_in[2];
    const float* asr1 = (const float*)d_in[3];
    const float* adt1 = (const float*)d_in[4];
    const float* b1   = (const float*)d_in[5];
    const float* W2   = (const float*)d_in[6];
    const float* asr2 = (const float*)d_in[7];
    const float* adt2 = (const float*)d_in[8];
    const float* b2   = (const float*)d_in[9];
    float* out = (float*)d_out;

    const int n = in_sizes[0] / 128;
    const int E = in_sizes[1] / 2;
    const int* src = ei;
    const int* dst = ei + E;

    float *as1, *ad1, *as2, *ad2, *w1r, *w2r;
    __half *h1h, *hrh, *h2h;
    int *deg, *off, *pos, *ssrc, *bsum;
    cudaGetSymbolAddress((void**)&h1h,  g_h1h);
    cudaGetSymbolAddress((void**)&hrh,  g_hrh);
    cudaGetSymbolAddress((void**)&h2h,  g_h2h);
    cudaGetSymbolAddress((void**)&as1,  g_as1);
    cudaGetSymbolAddress((void**)&ad1,  g_ad1);
    cudaGetSymbolAddress((void**)&as2,  g_as2);
    cudaGetSymbolAddress((void**)&ad2,  g_ad2);
    cudaGetSymbolAddress((void**)&w1r,  g_w1r);
    cudaGetSymbolAddress((void**)&w2r,  g_w2r);
    cudaGetSymbolAddress((void**)&deg,  g_deg);
    cudaGetSymbolAddress((void**)&off,  g_off);
    cudaGetSymbolAddress((void**)&pos,  g_pos);
    cudaGetSymbolAddress((void**)&ssrc, g_ssrc);
    cudaGetSymbolAddress((void**)&bsum, g_bsum);

    const int GEMM_SMEM = (2 * 128 * 36 + 2 * 32 * 72) * 4;   // 55296 B

    static cudaStream_t s2 = nullptr;
    static cudaEvent_t evFork = nullptr, evJoin = nullptr;
    if (!s2) {
        cudaStreamCreateWithFlags(&s2, cudaStreamNonBlocking);
        cudaEventCreateWithFlags(&evFork, cudaEventDisableTiming);
        cudaEventCreateWithFlags(&evJoin, cudaEventDisableTiming);
        cudaFuncSetAttribute(gemm_tf32<64, 4, float>,
                             cudaFuncAttributeMaxDynamicSharedMemorySize, GEMM_SMEM);
        cudaFuncSetAttribute(gemm_tf32<32, 1, __half>,
                             cudaFuncAttributeMaxDynamicSharedMemorySize, GEMM_SMEM);
    }

    const int nb128 = (n + 127) / 128;
    const int eb = (E + 255) / 256;
    const int nwarp_blocks = (n * 32 + 127) / 128;   // 128-thread agg blocks
    const int nscan = (n + 255) / 256;
    const int SZ1 = 128 * 128, SZ2 = 128 * 32;

    // ---- fork: CSR build on side stream ----
    cudaEventRecord(evFork, 0);
    cudaStreamWaitEvent(s2, evFork, 0);
    cudaMemsetAsync(deg, 0, n * sizeof(int), s2);
    hist_kernel<<<eb, 256, 0, s2>>>(dst, E, deg);
    scan_part<<<nscan, 256, 0, s2>>>(deg, bsum, n);
    scan_mid<<<1, 512, 0, s2>>>(bsum, nscan);
    scan_final<<<nscan, 256, 0, s2>>>(deg, bsum, off, pos, n);
    scatter_kernel<<<eb, 256, 0, s2>>>(src, dst, E, pos, ssrc);
    cudaEventRecord(evJoin, s2);

    // ---- main stream: pre-round weights, then layer-1 GEMM (+fused dots) ----
    round_weights<<<(SZ1 + SZ2 + 255) / 256, 256>>>(W1, w1r, SZ1, W2, w2r, SZ2);
    gemm_tf32<64, 4, float><<<dim3(nb128, 2), 128, GEMM_SMEM>>>(
        x, w1r, h1h, asr1, adt1, as1, ad1, n, 128);

    // ---- join ----
    cudaStreamWaitEvent(0, evJoin, 0);
    agg4<<<nwarp_blocks, 128>>>(off, ssrc, h1h, as1, ad1, b1, hrh, n);

    // ---- Layer 2 ----
    gemm_tf32<32, 1, __half><<<dim3(nb128, 1), 128, GEMM_SMEM>>>(
        hrh, w2r, h2h, asr2, adt2, as2, ad2, n, 32);
    agg1<<<nwarp_blocks, 128>>>(off, ssrc, h2h, as2, ad2, b2, out, n);
}